// round 2
// baseline (speedup 1.0000x reference)
#include <cuda_runtime.h>

// ---------------------------------------------------------------------------
// UHGAnomalyLoss:
//   loss = mean_E quad(p_src, p_dst) + mean_N quad(p, origin)
//          + 0.1 * mean_{first 10 edges} quad(line_src, line_dst)
// with p = (x, y, 1) from z[:, 0:2], origin = (0,0,1),
// inner(a,b) = -(a0 b0 + a1 b1) + a2 b2,
// quad(a,b) = (ab^2 - aa*bb) / (max(|aa*bb|, EPS) * sign(aa*bb)),
// line(p) = cross(p, origin) = (y, -x, 0).
// ---------------------------------------------------------------------------

#define N_NODES_C 200000
#define N_EDGES_C 12800000
#define DIM_C     128
#define EPSF      1e-9f

#define TPB       256
#define GRID_P    400     // prep kernel blocks
#define GRID_E    1184    // edge kernel blocks (148 SMs * 8)

// Scratch (device globals: no allocation allowed in kernel_launch)
__device__ float2 g_xy[N_NODES_C];
__device__ double g_prox_part[GRID_E];
__device__ double g_comp_part[GRID_P];

__device__ __forceinline__ float safe_den(float den) {
    return copysignf(fmaxf(fabsf(den), EPSF), den);
}

// ---------------------------------------------------------------------------
// Kernel 1: pack (x, y) into dense table + per-node compactness quadrance.
// compactness: aa = 1 - x^2 - y^2, bb = 1, ab = 1 -> quad = (1 - aa)/safe(aa)
// ---------------------------------------------------------------------------
__global__ void __launch_bounds__(TPB) prep_kernel(const float* __restrict__ z) {
    const int tid = blockIdx.x * TPB + threadIdx.x;
    double dsum = 0.0;
    for (int i = tid; i < N_NODES_C; i += GRID_P * TPB) {
        const float x = __ldg(&z[(size_t)i * DIM_C + 0]);
        const float y = __ldg(&z[(size_t)i * DIM_C + 1]);
        g_xy[i] = make_float2(x, y);
        const float aa  = 1.0f - x * x - y * y;
        const float num = 1.0f - aa;
        dsum += (double)__fdividef(num, safe_den(aa));
    }
    __shared__ double sh[TPB];
    sh[threadIdx.x] = dsum;
    __syncthreads();
    #pragma unroll
    for (int off = TPB / 2; off > 0; off >>= 1) {
        if (threadIdx.x < off) sh[threadIdx.x] += sh[threadIdx.x + off];
        __syncthreads();
    }
    if (threadIdx.x == 0) g_comp_part[blockIdx.x] = sh[0];
}

// ---------------------------------------------------------------------------
// Kernel 2: proximity quadrance over all edges (the hot loop).
// ---------------------------------------------------------------------------
__device__ __forceinline__ float quad_edge(int s, int d) {
    const float2 a = __ldg(&g_xy[s]);
    const float2 b = __ldg(&g_xy[d]);
    const float aa  = 1.0f - a.x * a.x - a.y * a.y;
    const float bb  = 1.0f - b.x * b.x - b.y * b.y;
    const float ab  = 1.0f - a.x * b.x - a.y * b.y;
    const float den = aa * bb;
    const float num = fmaf(ab, ab, -den);
    return __fdividef(num, safe_den(den));
}

__global__ void __launch_bounds__(TPB) edge_kernel(const int* __restrict__ ei) {
    const int4* __restrict__ src4 = (const int4*)ei;
    const int4* __restrict__ dst4 = (const int4*)(ei + N_EDGES_C);
    const int tid   = blockIdx.x * TPB + threadIdx.x;
    const int nIter = N_EDGES_C / 4;

    double dsum = 0.0;
    for (int i = tid; i < nIter; i += GRID_E * TPB) {
        const int4 s = __ldg(&src4[i]);
        const int4 d = __ldg(&dst4[i]);
        float part = quad_edge(s.x, d.x);
        part += quad_edge(s.y, d.y);
        part += quad_edge(s.z, d.z);
        part += quad_edge(s.w, d.w);
        dsum += (double)part;
    }

    __shared__ double sh[TPB];
    sh[threadIdx.x] = dsum;
    __syncthreads();
    #pragma unroll
    for (int off = TPB / 2; off > 0; off >>= 1) {
        if (threadIdx.x < off) sh[threadIdx.x] += sh[threadIdx.x + off];
        __syncthreads();
    }
    if (threadIdx.x == 0) g_prox_part[blockIdx.x] = sh[0];
}

// ---------------------------------------------------------------------------
// Kernel 3: reduce partials, spread over first 10 edges, write scalar loss.
// line(p) = (y, -x, 0): inner(la,lb) = -(ya*yb + xa*xb)  (time component 0)
// ---------------------------------------------------------------------------
__global__ void __launch_bounds__(TPB) finalize_kernel(const int* __restrict__ ei,
                                                       float* __restrict__ out) {
    __shared__ double sh[TPB];
    const int t = threadIdx.x;

    double p = 0.0;
    for (int i = t; i < GRID_E; i += TPB) p += g_prox_part[i];
    sh[t] = p;
    __syncthreads();
    #pragma unroll
    for (int off = TPB / 2; off > 0; off >>= 1) {
        if (t < off) sh[t] += sh[t + off];
        __syncthreads();
    }
    const double prox_sum = sh[0];
    __syncthreads();

    double c = 0.0;
    for (int i = t; i < GRID_P; i += TPB) c += g_comp_part[i];
    sh[t] = c;
    __syncthreads();
    #pragma unroll
    for (int off = TPB / 2; off > 0; off >>= 1) {
        if (t < off) sh[t] += sh[t + off];
        __syncthreads();
    }
    const double comp_sum = sh[0];

    if (t == 0) {
        double ssum = 0.0;
        const int n_sp = 10;  // min(10, E)
        for (int k = 0; k < n_sp; k++) {
            const int s = ei[k];
            const int d = ei[N_EDGES_C + k];
            const float2 a = g_xy[s];
            const float2 b = g_xy[d];
            // lines: la = (a.y, -a.x, 0), lb = (b.y, -b.x, 0)
            const float aa  = -(a.y * a.y + a.x * a.x);
            const float bb  = -(b.y * b.y + b.x * b.x);
            const float ab  = -(a.y * b.y + a.x * b.x);
            const float den = aa * bb;
            const float num = fmaf(ab, ab, -den);
            ssum += (double)__fdividef(num, safe_den(den));
        }
        const double loss = prox_sum / (double)N_EDGES_C
                          + comp_sum / (double)N_NODES_C
                          + 0.1 * (ssum / (double)n_sp);
        out[0] = (float)loss;
    }
}

// ---------------------------------------------------------------------------
extern "C" void kernel_launch(void* const* d_in, const int* in_sizes, int n_in,
                              void* d_out, int out_size) {
    const float* z  = (const float*)d_in[0];
    const int*   ei = (const int*)d_in[1];
    float*       out = (float*)d_out;

    prep_kernel<<<GRID_P, TPB>>>(z);
    edge_kernel<<<GRID_E, TPB>>>(ei);
    finalize_kernel<<<1, TPB>>>(ei, out);
}

// round 3
// speedup vs baseline: 1.0003x; 1.0003x over previous
#include <cuda_runtime.h>

// ---------------------------------------------------------------------------
// UHGAnomalyLoss:
//   loss = mean_E quad(p_src, p_dst) + mean_N quad(p, origin)
//          + 0.1 * mean_{first 10 edges} quad(line_src, line_dst)
// p = (x, y, 1) from z[:, 0:2], origin = (0,0,1),
// inner(a,b) = -(a0 b0 + a1 b1) + a2 b2,
// quad(a,b) = (ab^2 - aa*bb) / (max(|aa*bb|, EPS)*sign(aa*bb)),
// line(p) = cross(p, origin) = (y, -x, 0).
// ---------------------------------------------------------------------------

#define N_NODES_C 200000
#define N_EDGES_C 12800000
#define DIM_C     128
#define EPSF      1e-9f

#define TPB       256
#define GRID_P    782     // ceil(200000 / 256): one node per thread
#define GRID_E    1184    // 148 SMs * 8

// Scratch (device globals: no allocation allowed anywhere)
__device__ float2   g_xy[N_NODES_C];
__device__ double   g_prox_part[GRID_E];
__device__ double   g_comp_part[GRID_P];
__device__ unsigned g_ticket;

__device__ __forceinline__ float safe_den(float den) {
    return copysignf(fmaxf(fabsf(den), EPSF), den);
}

__device__ __forceinline__ double block_reduce(double v) {
    __shared__ double sh[TPB];
    sh[threadIdx.x] = v;
    __syncthreads();
    #pragma unroll
    for (int off = TPB / 2; off > 0; off >>= 1) {
        if (threadIdx.x < off) sh[threadIdx.x] += sh[threadIdx.x + off];
        __syncthreads();
    }
    double r = sh[0];
    __syncthreads();
    return r;
}

// ---------------------------------------------------------------------------
// Kernel 1: pack (x,y) into dense table + per-node compactness partials.
// compactness: aa = 1 - x^2 - y^2, bb = ab = 1 -> quad = (1 - aa)/safe(aa)
// Also resets the finalize ticket (stream-ordered before the edge kernel).
// ---------------------------------------------------------------------------
__global__ void __launch_bounds__(TPB) prep_kernel(const float* __restrict__ z) {
    const int i = blockIdx.x * TPB + threadIdx.x;
    if (i == 0) g_ticket = 0u;

    double q = 0.0;
    if (i < N_NODES_C) {
        const float2 v = __ldg((const float2*)(z + (size_t)i * DIM_C));
        g_xy[i] = v;
        const float aa = 1.0f - v.x * v.x - v.y * v.y;
        q = (double)__fdividef(1.0f - aa, safe_den(aa));
    }
    const double s = block_reduce(q);
    if (threadIdx.x == 0) g_comp_part[blockIdx.x] = s;
}

// ---------------------------------------------------------------------------
// Kernel 2: proximity quadrance over all edges + last-block finalize.
// ---------------------------------------------------------------------------
__device__ __forceinline__ float quad_edge(int s, int d) {
    const float2 a = __ldg(&g_xy[s]);
    const float2 b = __ldg(&g_xy[d]);
    const float aa  = 1.0f - a.x * a.x - a.y * a.y;
    const float bb  = 1.0f - b.x * b.x - b.y * b.y;
    const float ab  = 1.0f - a.x * b.x - a.y * b.y;
    const float den = aa * bb;
    const float num = fmaf(ab, ab, -den);
    return __fdividef(num, safe_den(den));
}

__device__ __forceinline__ float quad4(int4 s, int4 d) {
    float p = quad_edge(s.x, d.x);
    p += quad_edge(s.y, d.y);
    p += quad_edge(s.z, d.z);
    p += quad_edge(s.w, d.w);
    return p;
}

__global__ void __launch_bounds__(TPB) edge_kernel(const int* __restrict__ ei,
                                                   float* __restrict__ out) {
    const int4* __restrict__ src4 = (const int4*)ei;
    const int4* __restrict__ dst4 = (const int4*)(ei + N_EDGES_C);
    const int tid    = blockIdx.x * TPB + threadIdx.x;
    const int nIter4 = N_EDGES_C / 4;          // 3.2M int4 records
    const int nHalf  = nIter4 / 2;             // two coalesced half-streams
    const int stride = GRID_E * TPB;

    double dsum = 0.0;
    for (int i = tid; i < nHalf; i += stride) {
        // Stream edge indices with evict-first hint: keep L1 for g_xy.
        const int4 s0 = __ldcs(&src4[i]);
        const int4 d0 = __ldcs(&dst4[i]);
        const int4 s1 = __ldcs(&src4[i + nHalf]);
        const int4 d1 = __ldcs(&dst4[i + nHalf]);
        dsum += (double)(quad4(s0, d0) + quad4(s1, d1));
    }

    const double bsum = block_reduce(dsum);
    if (threadIdx.x == 0) g_prox_part[blockIdx.x] = bsum;

    // ---- last-block finalize ----
    __shared__ bool s_last;
    __threadfence();
    if (threadIdx.x == 0)
        s_last = (atomicAdd(&g_ticket, 1u) == (unsigned)(GRID_E - 1));
    __syncthreads();
    if (!s_last) return;

    const int t = threadIdx.x;
    double p = 0.0;
    for (int i = t; i < GRID_E; i += TPB) p += g_prox_part[i];
    const double prox_sum = block_reduce(p);

    double c = 0.0;
    for (int i = t; i < GRID_P; i += TPB) c += g_comp_part[i];
    const double comp_sum = block_reduce(c);

    if (t == 0) {
        double ssum = 0.0;
        const int n_sp = 10;  // min(10, E)
        for (int k = 0; k < n_sp; k++) {
            const int s = ei[k];
            const int d = ei[N_EDGES_C + k];
            const float2 a = g_xy[s];
            const float2 b = g_xy[d];
            // lines: la = (a.y, -a.x, 0), lb = (b.y, -b.x, 0)
            const float aa  = -(a.y * a.y + a.x * a.x);
            const float bb  = -(b.y * b.y + b.x * b.x);
            const float ab  = -(a.y * b.y + a.x * b.x);
            const float den = aa * bb;
            const float num = fmaf(ab, ab, -den);
            ssum += (double)__fdividef(num, safe_den(den));
        }
        const double loss = prox_sum / (double)N_EDGES_C
                          + comp_sum / (double)N_NODES_C
                          + 0.1 * (ssum / (double)n_sp);
        out[0] = (float)loss;
    }
}

// ---------------------------------------------------------------------------
extern "C" void kernel_launch(void* const* d_in, const int* in_sizes, int n_in,
                              void* d_out, int out_size) {
    const float* z   = (const float*)d_in[0];
    const int*   ei  = (const int*)d_in[1];
    float*       out = (float*)d_out;

    prep_kernel<<<GRID_P, TPB>>>(z);
    edge_kernel<<<GRID_E, TPB>>>(ei, out);
}